// round 7
// baseline (speedup 1.0000x reference)
#include <cuda_runtime.h>
#include <cstdint>
#include <math.h>

#define BATCH 64
#define CCH   512
#define NPIX  1024
#define DD    64

// ---------------- scratch (static device arrays) ----------------
__device__ __align__(128) float g_q [BATCH * CCH * DD];
__device__ __align__(128) float g_k [BATCH * CCH * DD];
__device__ __align__(128) float g_at[(size_t)BATCH * CCH * CCH]; // unnormalized T, tf32
__device__ __align__(128) float g_m [(size_t)BATCH * CCH * CCH]; // M, tf32
__device__ __align__(128) float g_ab[BATCH * CCH];               // (T.b)/S per (b,j)
__device__ __align__(128) float g_inv[BATCH * CCH];              // 1/S per (b,j)
__device__ __align__(128) float g_ps [BATCH * CCH * 8];          // partial col sums
__device__ __align__(128) float g_psb[BATCH * CCH * 8];          // partial col bias dots
__device__ __align__(128) float g_wt[CCH * CCH];                 // W^T, tf32
__device__ __align__(128) float g_xt[(size_t)BATCH * NPIX * CCH];// x^T, tf32
__device__ __align__(128) float g_bhi[128 * NPIX];               // [Qm^T;Km^T] hi
__device__ __align__(128) float g_blo[128 * NPIX];               // [Qm^T;Km^T] lo

// ---------------- helpers ----------------
__device__ __forceinline__ float to_tf32(float x) {
    uint32_t u;
    asm("cvt.rna.tf32.f32 %0, %1;" : "=r"(u) : "f"(x));
    return __uint_as_float(u);
}
__device__ __forceinline__ uint32_t smem_u32(const void* p) {
    uint32_t a;
    asm("{ .reg .u64 t; cvta.to.shared.u64 t, %1; cvt.u32.u64 %0, t; }" : "=r"(a) : "l"(p));
    return a;
}
__device__ __forceinline__ void cpa16(uint32_t d, const void* g) {
    asm volatile("cp.async.cg.shared.global [%0], [%1], 16;" :: "r"(d), "l"(g) : "memory");
}
__device__ __forceinline__ void cpa_commit() {
    asm volatile("cp.async.commit_group;" ::: "memory");
}
__device__ __forceinline__ void mma_tf32(float* c, const uint32_t* a, const uint32_t* b) {
    asm volatile(
        "mma.sync.aligned.m16n8k8.row.col.f32.tf32.tf32.f32 "
        "{%0,%1,%2,%3}, {%4,%5,%6,%7}, {%8,%9}, {%0,%1,%2,%3};"
        : "+f"(c[0]), "+f"(c[1]), "+f"(c[2]), "+f"(c[3])
        : "r"(a[0]), "r"(a[1]), "r"(a[2]), "r"(a[3]), "r"(b[0]), "r"(b[1]));
}

// ============================================================================
// prep_b: g_bhi/g_blo[d'][n]: d'<64 -> Qm[n][d'], else Km[n][d'-64], split
// ============================================================================
__global__ __launch_bounds__(256) void prep_b(
    const float* __restrict__ qm, const float* __restrict__ km)
{
    const int n = blockIdx.x * 256 + threadIdx.x;
    const int d = blockIdx.y;
    float v = (d < 64) ? qm[n * 64 + d] : km[n * 64 + (d - 64)];
    float hi = to_tf32(v);
    g_bhi[d * NPIX + n] = hi;
    g_blo[d * NPIX + n] = v - hi;
}

// ============================================================================
// qk3x: [q|k] = x @ [Qm|Km] via 3xTF32 MMA. Tile 128(c) x 128(d'), BK=32.
// 3-buffer pipeline, ONE __syncthreads per stage. grid (4, BATCH), 192KB smem.
// ============================================================================
__global__ __launch_bounds__(256) void qk3x_kernel(const float* __restrict__ x)
{
    extern __shared__ __align__(16) float qs[];
    // per buffer (floats): Ahi[0,4096) Alo[4096,8192) Bhi[8192,12288) Blo[12288,16384)
    const int b = blockIdx.y;
    const int row0 = blockIdx.x * 128;
    const float* A = x + (size_t)b * CCH * NPIX + (size_t)row0 * NPIX;

    const int tid = threadIdx.x;
    const int wid = tid >> 5, lid = tid & 31;
    const int gid = lid >> 2, tig = lid & 3;
    const int wm = wid >> 2, wn = wid & 3;

    const uint32_t sb = smem_u32(qs);
    const int lr = tid >> 3, lc = tid & 7;   // base row, 16B-chunk

    float4 va[4];
    auto ldgA = [&](int s) {
        const int k0 = s * 32;
#pragma unroll
        for (int q = 0; q < 4; q++)
            va[q] = *(const float4*)&A[(size_t)(lr + q * 32) * NPIX + k0 + lc * 4];
    };
    auto stsA = [&](int buf) {
#pragma unroll
        for (int q = 0; q < 4; q++) {
            const int row = lr + q * 32;
            float* hi = qs + buf * 16384 + row * 32 + ((lc ^ (row & 7)) << 2);
            float* lo = hi + 4096;
            float4 h, l;
            h.x = to_tf32(va[q].x); l.x = va[q].x - h.x;
            h.y = to_tf32(va[q].y); l.y = va[q].y - h.y;
            h.z = to_tf32(va[q].z); l.z = va[q].z - h.z;
            h.w = to_tf32(va[q].w); l.w = va[q].w - h.w;
            *(float4*)hi = h;
            *(float4*)lo = l;
        }
    };
    auto cpaB = [&](int s, int buf) {
        const int k0 = s * 32;
#pragma unroll
        for (int q = 0; q < 4; q++) {
            const int row = lr + q * 32;
            const uint32_t off = (uint32_t)((row * 32 + ((lc ^ (row & 7)) << 2)) * 4);
            cpa16(sb + (buf * 16384 + 8192)  * 4 + off, &g_bhi[row * NPIX + k0 + lc * 4]);
            cpa16(sb + (buf * 16384 + 12288) * 4 + off, &g_blo[row * NPIX + k0 + lc * 4]);
        }
        cpa_commit();
    };

    float acc[4][4][4] = {};
    int mrow[4], ncol[4];
#pragma unroll
    for (int i = 0; i < 4; i++) {
        mrow[i] = wm * 64 + i * 16 + gid;
        ncol[i] = wn * 32 + i * 8 + gid;
    }

    // prologue: stages 0 and 1
    ldgA(0); cpaB(0, 0); stsA(0);
    ldgA(1); cpaB(1, 1); stsA(1);

    for (int s = 0; s < 32; s++) {
        const int buf = s % 3;
        if (s + 2 < 32) ldgA(s + 2);
        if (s < 31) { asm volatile("cp.async.wait_group 1;" ::: "memory"); }
        else        { asm volatile("cp.async.wait_group 0;" ::: "memory"); }
        __syncthreads();
        if (s + 2 < 32) { cpaB(s + 2, (s + 2) % 3); stsA((s + 2) % 3); }

        const float* ahs = qs + buf * 16384;
        const float* als = ahs + 4096;
        const float* bhs = ahs + 8192;
        const float* bls = ahs + 12288;
#pragma unroll
        for (int kk = 0; kk < 4; kk++) {
            const int c0 = 2 * kk, c1 = 2 * kk + 1;
            uint32_t ah[4][4], al[4][4], bh[4][2], bl[4][2];
#pragma unroll
            for (int mi = 0; mi < 4; mi++) {
                const int r1 = mrow[mi], r2 = r1 + 8;
                const int o10 = r1 * 32 + ((c0 ^ (r1 & 7)) << 2) + tig;
                const int o20 = r2 * 32 + ((c0 ^ (r2 & 7)) << 2) + tig;
                const int o11 = r1 * 32 + ((c1 ^ (r1 & 7)) << 2) + tig;
                const int o21 = r2 * 32 + ((c1 ^ (r2 & 7)) << 2) + tig;
                ah[mi][0] = __float_as_uint(ahs[o10]); al[mi][0] = __float_as_uint(als[o10]);
                ah[mi][1] = __float_as_uint(ahs[o20]); al[mi][1] = __float_as_uint(als[o20]);
                ah[mi][2] = __float_as_uint(ahs[o11]); al[mi][2] = __float_as_uint(als[o11]);
                ah[mi][3] = __float_as_uint(ahs[o21]); al[mi][3] = __float_as_uint(als[o21]);
            }
#pragma unroll
            for (int ni = 0; ni < 4; ni++) {
                const int cc = ncol[ni];
                const int p0 = cc * 32 + ((c0 ^ (cc & 7)) << 2) + tig;
                const int p1 = cc * 32 + ((c1 ^ (cc & 7)) << 2) + tig;
                bh[ni][0] = __float_as_uint(bhs[p0]); bl[ni][0] = __float_as_uint(bls[p0]);
                bh[ni][1] = __float_as_uint(bhs[p1]); bl[ni][1] = __float_as_uint(bls[p1]);
            }
#pragma unroll
            for (int mi = 0; mi < 4; mi++)
#pragma unroll
                for (int ni = 0; ni < 4; ni++) {
                    mma_tf32(acc[mi][ni], ah[mi], bh[ni]);
                    mma_tf32(acc[mi][ni], ah[mi], bl[ni]);
                    mma_tf32(acc[mi][ni], al[mi], bh[ni]);
                }
        }
    }

    // epilogue: cols <64 -> g_q, >=64 -> g_k
#pragma unroll
    for (int mi = 0; mi < 4; mi++) {
        const int r1 = row0 + wm * 64 + mi * 16 + gid;
        const int r2 = r1 + 8;
#pragma unroll
        for (int ni = 0; ni < 4; ni++) {
            const int d = wn * 32 + ni * 8 + tig * 2;
            float* base = (d < 64) ? g_q : g_k;
            const int dc = d & 63;
            float* p1 = base + ((size_t)b * CCH + r1) * DD + dc;
            float* p2 = base + ((size_t)b * CCH + r2) * DD + dc;
            *(float2*)p1 = make_float2(acc[mi][ni][0], acc[mi][ni][1]);
            *(float2*)p2 = make_float2(acc[mi][ni][2], acc[mi][ni][3]);
        }
    }
}

// ============================================================================
// energy: At[b][j][i] = tf32(exp(sigmoid(e))) unnormalized; partial col sums.
// ============================================================================
__global__ __launch_bounds__(256) void energy_kernel(const float* __restrict__ vb)
{
    __shared__ float Qs[16][64];
    __shared__ float Ks[16][64];
    __shared__ float Cs[64][68];

    const int b  = blockIdx.z;
    const int j0 = blockIdx.x * 64;
    const int i0 = blockIdx.y * 64;
    const float* Aq = g_q + ((size_t)b * CCH + i0) * DD;
    const float* Ak = g_k + ((size_t)b * CCH + j0) * DD;

    const int tid = threadIdx.x;
    const int ty = tid / 16, tx = tid % 16;
    const int ar = tid / 4,  ac = (tid % 4) * 4;

    float e[4][4] = {};
    for (int k0 = 0; k0 < DD; k0 += 16) {
        float4 av = *(const float4*)&Aq[ar * DD + k0 + ac];
        Qs[ac + 0][ar] = av.x; Qs[ac + 1][ar] = av.y;
        Qs[ac + 2][ar] = av.z; Qs[ac + 3][ar] = av.w;
        float4 bv = *(const float4*)&Ak[ar * DD + k0 + ac];
        Ks[ac + 0][ar] = bv.x; Ks[ac + 1][ar] = bv.y;
        Ks[ac + 2][ar] = bv.z; Ks[ac + 3][ar] = bv.w;
        __syncthreads();
#pragma unroll
        for (int kk = 0; kk < 16; kk++) {
            float a[4], bb[4];
#pragma unroll
            for (int u = 0; u < 4; u++) a[u]  = Qs[kk][ty * 4 + u];
#pragma unroll
            for (int v = 0; v < 4; v++) bb[v] = Ks[kk][tx * 4 + v];
#pragma unroll
            for (int u = 0; u < 4; u++)
#pragma unroll
                for (int v = 0; v < 4; v++) e[u][v] = fmaf(a[u], bb[v], e[u][v]);
        }
        __syncthreads();
    }

    float t[4][4];
    bool need = false;
#pragma unroll
    for (int u = 0; u < 4; u++)
#pragma unroll
        for (int v = 0; v < 4; v++) need |= (fabsf(e[u][v]) < 12.0f);
    if (__any_sync(0xffffffffu, need)) {
#pragma unroll
        for (int u = 0; u < 4; u++)
#pragma unroll
            for (int v = 0; v < 4; v++) {
                float s = 1.0f / (1.0f + __expf(-e[u][v]));
                t[u][v] = __expf(s);
            }
    } else {
#pragma unroll
        for (int u = 0; u < 4; u++)
#pragma unroll
            for (int v = 0; v < 4; v++)
                t[u][v] = (e[u][v] > 0.0f) ? 2.71828182845904523536f : 1.0f;
    }
#pragma unroll
    for (int u = 0; u < 4; u++)
#pragma unroll
        for (int v = 0; v < 4; v++)
            Cs[tx * 4 + v][ty * 4 + u] = to_tf32(t[u][v]);
    __syncthreads();

    float* orow = g_at + ((size_t)b * CCH) * CCH;
    const int jj = tid / 4;
    const int st = (tid % 4) * 16;
    float* dst = &orow[(size_t)(j0 + jj) * CCH + i0 + st];
    float s = 0.0f, sbias = 0.0f;
#pragma unroll
    for (int w = 0; w < 4; w++) {
        float4 v4 = *(float4*)&Cs[jj][st + w * 4];
        const float* bb = &vb[i0 + st + w * 4];
        s += v4.x + v4.y + v4.z + v4.w;
        sbias += v4.x * bb[0] + v4.y * bb[1] + v4.z * bb[2] + v4.w * bb[3];
        *(float4*)&dst[w * 4] = v4;
    }
    s += __shfl_xor_sync(0xffffffffu, s, 1);
    s += __shfl_xor_sync(0xffffffffu, s, 2);
    sbias += __shfl_xor_sync(0xffffffffu, sbias, 1);
    sbias += __shfl_xor_sync(0xffffffffu, sbias, 2);
    if ((tid & 3) == 0) {
        const int idx = ((b << 9) + j0 + jj) * 8 + blockIdx.y;
        g_ps[idx]  = s;
        g_psb[idx] = sbias;
    }
}

// ============================================================================
// reduce: S, TB -> g_inv = 1/S, g_ab = TB/S
// ============================================================================
__global__ __launch_bounds__(256) void reduce_kernel()
{
    const int idx = blockIdx.x * 256 + threadIdx.x;
    float S = 0.0f, TB = 0.0f;
#pragma unroll
    for (int r = 0; r < 8; r++) { S += g_ps[idx * 8 + r]; TB += g_psb[idx * 8 + r]; }
    g_inv[idx] = 1.0f / S;
    g_ab[idx]  = TB / S;
}

// ============================================================================
// Transposes
// ============================================================================
__global__ __launch_bounds__(256) void wt_kernel(const float* __restrict__ W)
{
    __shared__ float t[32][33];
    const int x0 = blockIdx.x * 32, y0 = blockIdx.y * 32;
    const int tx = threadIdx.x, ty = threadIdx.y;
#pragma unroll
    for (int r = 0; r < 32; r += 8) t[ty + r][tx] = W[(y0 + ty + r) * CCH + x0 + tx];
    __syncthreads();
#pragma unroll
    for (int r = 0; r < 32; r += 8)
        g_wt[(x0 + ty + r) * CCH + y0 + tx] = to_tf32(t[tx][ty + r]);
}

__global__ __launch_bounds__(256) void xt_kernel(const float* __restrict__ x)
{
    __shared__ float t[32][33];
    const int b = blockIdx.z;
    const float* in = x + (size_t)b * CCH * NPIX;
    float* out = g_xt + (size_t)b * NPIX * CCH;
    const int n0 = blockIdx.x * 32, c0 = blockIdx.y * 32;
    const int tx = threadIdx.x, ty = threadIdx.y;
#pragma unroll
    for (int r = 0; r < 32; r += 8) t[ty + r][tx] = in[(size_t)(c0 + ty + r) * NPIX + n0 + tx];
    __syncthreads();
#pragma unroll
    for (int r = 0; r < 32; r += 8)
        out[(size_t)(n0 + ty + r) * CCH + c0 + tx] = to_tf32(t[tx][ty + r]);
}

// ============================================================================
// gemm_mma v2: block 128x256, warp tile 64x64 (8 warps 2x4), BK=32,
// 3-stage cp.async (144KB smem), one __syncthreads per stage, 1 CTA/SM.
// which==0: M = (At @ Wt) * (1/S_j), tf32 -> g_m   [grid (2,4,64)]
// which==1: out = M @ xT + ab                      [grid (4,4,64)]
// Per stage (floats): A[0,4096) B[4096,12288); stage stride 12288.
// ============================================================================
__global__ __launch_bounds__(256) void gemm_mma(int which, float* __restrict__ outp)
{
    extern __shared__ __align__(16) float sm[];

    const int b = blockIdx.z;
    const int col0 = blockIdx.x * 256, row0 = blockIdx.y * 128;

    const float* A; const float* B; float* C; int ldc;
    if (which == 0) {
        A = g_at + (size_t)b * CCH * CCH;
        B = g_wt;
        C = g_m + (size_t)b * CCH * CCH;
        ldc = CCH;
    } else {
        A = g_m + (size_t)b * CCH * CCH;
        B = g_xt + (size_t)b * NPIX * CCH;
        C = outp + (size_t)b * CCH * NPIX;
        ldc = NPIX;
    }
    const float* Ab = A + (size_t)row0 * CCH;
    const float* Bb = B + (size_t)col0 * CCH;

    const int tid = threadIdx.x;
    const int wid = tid >> 5, lid = tid & 31;
    const int gid = lid >> 2, tig = lid & 3;
    const int wm = wid >> 2, wn = wid & 3;   // 2 x 4 warps, 64x64 each

    const uint32_t sb = smem_u32(sm);
    const int ldrow = tid >> 3, ldch = tid & 7;
    const uint32_t swz = (uint32_t)((ldrow * 32 + ((ldch ^ (ldrow & 7)) << 2)) * 4);

    auto issue = [&](int s, int buf) {
        const int k0 = s * 32;
        const uint32_t abase = sb + buf * 49152 + swz;
        const uint32_t bbase = sb + buf * 49152 + 16384 + swz;
#pragma unroll
        for (int q = 0; q < 4; q++)
            cpa16(abase + q * 32 * 128, &Ab[(size_t)(ldrow + q * 32) * CCH + k0 + ldch * 4]);
#pragma unroll
        for (int q = 0; q < 8; q++)
            cpa16(bbase + q * 32 * 128, &Bb[(size_t)(ldrow + q * 32) * CCH + k0 + ldch * 4]);
        cpa_commit();
    };

    float acc[4][8][4] = {};
    int mrow[4], ncol[8];
#pragma unroll
    for (int i = 0; i < 4; i++) mrow[i] = wm * 64 + i * 16 + gid;
#pragma unroll
    for (int i = 0; i < 8; i++) ncol[i] = wn * 64 + i * 8 + gid;

    issue(0, 0);
    issue(1, 1);

    for (int s = 0; s < 16; s++) {
        const int buf = s % 3;
        if (s < 15) { asm volatile("cp.async.wait_group 1;" ::: "memory"); }
        else        { asm volatile("cp.async.wait_group 0;" ::: "memory"); }
        __syncthreads();
        if (s + 2 < 16) issue(s + 2, (s + 2) % 3);

        const float* as = sm + buf * 12288;
        const float* bs = as + 4096;
#pragma unroll
        for (int kk = 0; kk < 4; kk++) {
            const int c0 = 2 * kk, c1 = 2 * kk + 1;
            uint32_t af[4][4], bf[8][2];
#pragma unroll
            for (int mi = 0; mi < 4; mi++) {
                const int r1 = mrow[mi], r2 = r1 + 8;
                af[mi][0] = __float_as_uint(as[r1 * 32 + ((c0 ^ (r1 & 7)) << 2) + tig]);
                af[mi][1] = __float_as_uint(as[r2 * 32 + ((c0 ^ (r2 & 7)) << 2) + tig]);
                af[mi][2] = __float_as_uint(as[r1 * 32 + ((c1 ^ (r1 & 7)) << 2) + tig]);
                af[mi][3] = __float_as_uint(as[r2 * 32 + ((c1 ^ (r2 & 7)) << 2) + tig]);
            }
#pragma unroll
            for (int nf = 0; nf < 8; nf++) {
                const int cc = ncol[nf];
                bf[nf][0] = __float_as_uint(bs[cc * 32 + ((c0 ^ (cc & 7)) << 2) + tig]);
                bf[nf][1] = __float_as_uint(bs[cc * 32 + ((c1 ^ (cc & 7)) << 2) + tig]);
            }
#pragma unroll
            for (int mi = 0; mi < 4; mi++)
#pragma unroll
                for (int nf = 0; nf < 8; nf++)
                    mma_tf32(acc[mi][nf], af[mi], bf[nf]);
        }
    }

    // epilogue
#pragma unroll
    for (int mi = 0; mi < 4; mi++) {
        const int r1 = row0 + wm * 64 + mi * 16 + gid;
        const int r2 = r1 + 8;
        float s1, s2;
        if (which == 0) { s1 = g_inv[(b << 9) + r1]; s2 = g_inv[(b << 9) + r2]; }
        else            { s1 = g_ab [(b << 9) + r1]; s2 = g_ab [(b << 9) + r2]; }
#pragma unroll
        for (int nf = 0; nf < 8; nf++) {
            const int cc = col0 + wn * 64 + nf * 8 + tig * 2;
            float* p1 = &C[(size_t)r1 * ldc + cc];
            float* p2 = &C[(size_t)r2 * ldc + cc];
            float c0 = acc[mi][nf][0], c1 = acc[mi][nf][1];
            float c2 = acc[mi][nf][2], c3 = acc[mi][nf][3];
            if (which == 0) {
                c0 = to_tf32(c0 * s1); c1 = to_tf32(c1 * s1);
                c2 = to_tf32(c2 * s2); c3 = to_tf32(c3 * s2);
            } else {
                c0 += s1; c1 += s1; c2 += s2; c3 += s2;
            }
            *(float2*)p1 = make_float2(c0, c1);
            *(float2*)p2 = make_float2(c2, c3);
        }
    }
}

// ============================================================================
extern "C" void kernel_launch(void* const* d_in, const int* in_sizes, int n_in,
                              void* d_out, int out_size)
{
    const float* x  = (const float*)d_in[0];
    const float* qm = (const float*)d_in[1];
    const float* km = (const float*)d_in[2];
    const float* vw = (const float*)d_in[3];
    const float* vb = (const float*)d_in[4];
    float* out = (float*)d_out;

    cudaFuncSetAttribute(gemm_mma,    cudaFuncAttributeMaxDynamicSharedMemorySize, 147456);
    cudaFuncSetAttribute(qk3x_kernel, cudaFuncAttributeMaxDynamicSharedMemorySize, 196608);

    prep_b       <<<dim3(NPIX / 256, 128),           256>>>(qm, km);
    qk3x_kernel  <<<dim3(4, BATCH),                  256, 196608>>>(x);
    energy_kernel<<<dim3(CCH / 64, CCH / 64, BATCH), 256>>>(vb);
    reduce_kernel<<<dim3(BATCH * CCH / 256),         256>>>();
    wt_kernel    <<<dim3(16, 16),        dim3(32, 8)>>>(vw);
    xt_kernel    <<<dim3(32, 16, BATCH), dim3(32, 8)>>>(x);
    gemm_mma<<<dim3(CCH / 256,  CCH / 128, BATCH), 256, 147456>>>(0, nullptr);
    gemm_mma<<<dim3(NPIX / 256, CCH / 128, BATCH), 256, 147456>>>(1, out);
}

// round 9
// speedup vs baseline: 1.0828x; 1.0828x over previous
#include <cuda_runtime.h>
#include <cstdint>
#include <math.h>

#define BATCH 64
#define CCH   512
#define NPIX  1024
#define DD    64

// ---------------- scratch (static device arrays) ----------------
__device__ __align__(128) float g_q [BATCH * CCH * DD];
__device__ __align__(128) float g_k [BATCH * CCH * DD];
__device__ __align__(128) float g_at[(size_t)BATCH * CCH * CCH]; // unnormalized T, tf32
__device__ __align__(128) float g_m [(size_t)BATCH * CCH * CCH]; // M, tf32
__device__ __align__(128) float g_ab[BATCH * CCH];               // (T.b)/S per (b,j)
__device__ __align__(128) float g_inv[BATCH * CCH];              // 1/S per (b,j)
__device__ __align__(128) float g_ps [BATCH * CCH * 8];          // partial col sums
__device__ __align__(128) float g_psb[BATCH * CCH * 8];          // partial col bias dots
__device__ __align__(128) float g_wt[CCH * CCH];                 // W^T, tf32
__device__ __align__(128) float g_xt[(size_t)BATCH * NPIX * CCH];// x^T, tf32
__device__ __align__(128) float g_bhi[128 * NPIX];               // [Qm^T;Km^T] hi
__device__ __align__(128) float g_blo[128 * NPIX];               // [Qm^T;Km^T] lo

// ---------------- helpers ----------------
__device__ __forceinline__ float to_tf32(float x) {
    uint32_t u;
    asm("cvt.rna.tf32.f32 %0, %1;" : "=r"(u) : "f"(x));
    return __uint_as_float(u);
}
__device__ __forceinline__ uint32_t smem_u32(const void* p) {
    uint32_t a;
    asm("{ .reg .u64 t; cvta.to.shared.u64 t, %1; cvt.u32.u64 %0, t; }" : "=r"(a) : "l"(p));
    return a;
}
__device__ __forceinline__ void cpa16(uint32_t d, const void* g) {
    asm volatile("cp.async.cg.shared.global [%0], [%1], 16;" :: "r"(d), "l"(g) : "memory");
}
__device__ __forceinline__ void cpa_commit() {
    asm volatile("cp.async.commit_group;" ::: "memory");
}
__device__ __forceinline__ void mma_tf32(float* c, const uint32_t* a, const uint32_t* b) {
    asm volatile(
        "mma.sync.aligned.m16n8k8.row.col.f32.tf32.tf32.f32 "
        "{%0,%1,%2,%3}, {%4,%5,%6,%7}, {%8,%9}, {%0,%1,%2,%3};"
        : "+f"(c[0]), "+f"(c[1]), "+f"(c[2]), "+f"(c[3])
        : "r"(a[0]), "r"(a[1]), "r"(a[2]), "r"(a[3]), "r"(b[0]), "r"(b[1]));
}

// ============================================================================
// prep_b: g_bhi/g_blo[d'][n]: d'<64 -> Qm[n][d'], else Km[n][d'-64], split
// ============================================================================
__global__ __launch_bounds__(256) void prep_b(
    const float* __restrict__ qm, const float* __restrict__ km)
{
    const int n = blockIdx.x * 256 + threadIdx.x;
    const int d = blockIdx.y;
    float v = (d < 64) ? qm[n * 64 + d] : km[n * 64 + (d - 64)];
    float hi = to_tf32(v);
    g_bhi[d * NPIX + n] = hi;
    g_blo[d * NPIX + n] = v - hi;
}

// ============================================================================
// qk3x: [q|k] = x @ [Qm|Km] via 3xTF32 MMA. Tile 128(c) x 128(d'), BK=32.
// R5-proven version: double buffer, 128KB smem. grid (4, BATCH).
// ============================================================================
__global__ __launch_bounds__(256) void qk3x_kernel(const float* __restrict__ x)
{
    extern __shared__ __align__(16) float qs[];
    // per buffer (floats): Ahi[0,4096) Alo[4096,8192) Bhi[8192,12288) Blo[12288,16384)
    const int b = blockIdx.y;
    const int row0 = blockIdx.x * 128;
    const float* A = x + (size_t)b * CCH * NPIX + (size_t)row0 * NPIX;

    const int tid = threadIdx.x;
    const int wid = tid >> 5, lid = tid & 31;
    const int gid = lid >> 2, tig = lid & 3;
    const int wm = wid >> 2, wn = wid & 3;

    const uint32_t sb = smem_u32(qs);
    const int lr = tid >> 3, lc = tid & 7;   // base row, 16B-chunk

    float4 va[4];
    auto ldgA = [&](int s) {
        const int k0 = s * 32;
#pragma unroll
        for (int q = 0; q < 4; q++)
            va[q] = *(const float4*)&A[(size_t)(lr + q * 32) * NPIX + k0 + lc * 4];
    };
    auto stsA = [&](int buf) {
#pragma unroll
        for (int q = 0; q < 4; q++) {
            const int row = lr + q * 32;
            float* hi = qs + buf * 16384 + row * 32 + ((lc ^ (row & 7)) << 2);
            float* lo = hi + 4096;
            float4 h, l;
            h.x = to_tf32(va[q].x); l.x = va[q].x - h.x;
            h.y = to_tf32(va[q].y); l.y = va[q].y - h.y;
            h.z = to_tf32(va[q].z); l.z = va[q].z - h.z;
            h.w = to_tf32(va[q].w); l.w = va[q].w - h.w;
            *(float4*)hi = h;
            *(float4*)lo = l;
        }
    };
    auto cpaB = [&](int s, int buf) {
        const int k0 = s * 32;
#pragma unroll
        for (int q = 0; q < 4; q++) {
            const int row = lr + q * 32;
            const uint32_t off = (uint32_t)((row * 32 + ((lc ^ (row & 7)) << 2)) * 4);
            cpa16(sb + (buf * 16384 + 8192)  * 4 + off, &g_bhi[row * NPIX + k0 + lc * 4]);
            cpa16(sb + (buf * 16384 + 12288) * 4 + off, &g_blo[row * NPIX + k0 + lc * 4]);
        }
        cpa_commit();
    };

    float acc[4][4][4] = {};
    int mrow[4], ncol[4];
#pragma unroll
    for (int i = 0; i < 4; i++) {
        mrow[i] = wm * 64 + i * 16 + gid;
        ncol[i] = wn * 32 + i * 8 + gid;
    }

    ldgA(0);
    cpaB(0, 0);
    stsA(0);

    for (int s = 0; s < 32; s++) {
        const int buf = s & 1;
        asm volatile("cp.async.wait_group 0;" ::: "memory");
        __syncthreads();
        if (s < 31) { ldgA(s + 1); cpaB(s + 1, buf ^ 1); }

        const float* ahs = qs + buf * 16384;
        const float* als = ahs + 4096;
        const float* bhs = ahs + 8192;
        const float* bls = ahs + 12288;
#pragma unroll
        for (int kk = 0; kk < 4; kk++) {
            const int c0 = 2 * kk, c1 = 2 * kk + 1;
            uint32_t ah[4][4], al[4][4], bh[4][2], bl[4][2];
#pragma unroll
            for (int mi = 0; mi < 4; mi++) {
                const int r1 = mrow[mi], r2 = r1 + 8;
                const int o10 = r1 * 32 + ((c0 ^ (r1 & 7)) << 2) + tig;
                const int o20 = r2 * 32 + ((c0 ^ (r2 & 7)) << 2) + tig;
                const int o11 = r1 * 32 + ((c1 ^ (r1 & 7)) << 2) + tig;
                const int o21 = r2 * 32 + ((c1 ^ (r2 & 7)) << 2) + tig;
                ah[mi][0] = __float_as_uint(ahs[o10]); al[mi][0] = __float_as_uint(als[o10]);
                ah[mi][1] = __float_as_uint(ahs[o20]); al[mi][1] = __float_as_uint(als[o20]);
                ah[mi][2] = __float_as_uint(ahs[o11]); al[mi][2] = __float_as_uint(als[o11]);
                ah[mi][3] = __float_as_uint(ahs[o21]); al[mi][3] = __float_as_uint(als[o21]);
            }
#pragma unroll
            for (int ni = 0; ni < 4; ni++) {
                const int cc = ncol[ni];
                const int p0 = cc * 32 + ((c0 ^ (cc & 7)) << 2) + tig;
                const int p1 = cc * 32 + ((c1 ^ (cc & 7)) << 2) + tig;
                bh[ni][0] = __float_as_uint(bhs[p0]); bl[ni][0] = __float_as_uint(bls[p0]);
                bh[ni][1] = __float_as_uint(bhs[p1]); bl[ni][1] = __float_as_uint(bls[p1]);
            }
#pragma unroll
            for (int mi = 0; mi < 4; mi++)
#pragma unroll
                for (int ni = 0; ni < 4; ni++) {
                    mma_tf32(acc[mi][ni], ah[mi], bh[ni]);
                    mma_tf32(acc[mi][ni], ah[mi], bl[ni]);
                    mma_tf32(acc[mi][ni], al[mi], bh[ni]);
                }
        }
        __syncthreads();
        if (s < 31) stsA(buf ^ 1);
    }

    // epilogue: cols <64 -> g_q, >=64 -> g_k
#pragma unroll
    for (int mi = 0; mi < 4; mi++) {
        const int r1 = row0 + wm * 64 + mi * 16 + gid;
        const int r2 = r1 + 8;
#pragma unroll
        for (int ni = 0; ni < 4; ni++) {
            const int d = wn * 32 + ni * 8 + tig * 2;
            float* base = (d < 64) ? g_q : g_k;
            const int dc = d & 63;
            float* p1 = base + ((size_t)b * CCH + r1) * DD + dc;
            float* p2 = base + ((size_t)b * CCH + r2) * DD + dc;
            *(float2*)p1 = make_float2(acc[mi][ni][0], acc[mi][ni][1]);
            *(float2*)p2 = make_float2(acc[mi][ni][2], acc[mi][ni][3]);
        }
    }
}

// ============================================================================
// energy: At[b][j][i] = tf32(exp(sigmoid(e))) unnormalized; partial col sums.
// ============================================================================
__global__ __launch_bounds__(256) void energy_kernel(const float* __restrict__ vb)
{
    __shared__ float Qs[16][64];
    __shared__ float Ks[16][64];
    __shared__ float Cs[64][68];

    const int b  = blockIdx.z;
    const int j0 = blockIdx.x * 64;
    const int i0 = blockIdx.y * 64;
    const float* Aq = g_q + ((size_t)b * CCH + i0) * DD;
    const float* Ak = g_k + ((size_t)b * CCH + j0) * DD;

    const int tid = threadIdx.x;
    const int ty = tid / 16, tx = tid % 16;
    const int ar = tid / 4,  ac = (tid % 4) * 4;

    float e[4][4] = {};
    for (int k0 = 0; k0 < DD; k0 += 16) {
        float4 av = *(const float4*)&Aq[ar * DD + k0 + ac];
        Qs[ac + 0][ar] = av.x; Qs[ac + 1][ar] = av.y;
        Qs[ac + 2][ar] = av.z; Qs[ac + 3][ar] = av.w;
        float4 bv = *(const float4*)&Ak[ar * DD + k0 + ac];
        Ks[ac + 0][ar] = bv.x; Ks[ac + 1][ar] = bv.y;
        Ks[ac + 2][ar] = bv.z; Ks[ac + 3][ar] = bv.w;
        __syncthreads();
#pragma unroll
        for (int kk = 0; kk < 16; kk++) {
            float a[4], bb[4];
#pragma unroll
            for (int u = 0; u < 4; u++) a[u]  = Qs[kk][ty * 4 + u];
#pragma unroll
            for (int v = 0; v < 4; v++) bb[v] = Ks[kk][tx * 4 + v];
#pragma unroll
            for (int u = 0; u < 4; u++)
#pragma unroll
                for (int v = 0; v < 4; v++) e[u][v] = fmaf(a[u], bb[v], e[u][v]);
        }
        __syncthreads();
    }

    float t[4][4];
    bool need = false;
#pragma unroll
    for (int u = 0; u < 4; u++)
#pragma unroll
        for (int v = 0; v < 4; v++) need |= (fabsf(e[u][v]) < 12.0f);
    if (__any_sync(0xffffffffu, need)) {
#pragma unroll
        for (int u = 0; u < 4; u++)
#pragma unroll
            for (int v = 0; v < 4; v++) {
                float s = 1.0f / (1.0f + __expf(-e[u][v]));
                t[u][v] = __expf(s);
            }
    } else {
#pragma unroll
        for (int u = 0; u < 4; u++)
#pragma unroll
            for (int v = 0; v < 4; v++)
                t[u][v] = (e[u][v] > 0.0f) ? 2.71828182845904523536f : 1.0f;
    }
#pragma unroll
    for (int u = 0; u < 4; u++)
#pragma unroll
        for (int v = 0; v < 4; v++)
            Cs[tx * 4 + v][ty * 4 + u] = to_tf32(t[u][v]);
    __syncthreads();

    float* orow = g_at + ((size_t)b * CCH) * CCH;
    const int jj = tid / 4;
    const int st = (tid % 4) * 16;
    float* dst = &orow[(size_t)(j0 + jj) * CCH + i0 + st];
    float s = 0.0f, sbias = 0.0f;
#pragma unroll
    for (int w = 0; w < 4; w++) {
        float4 v4 = *(float4*)&Cs[jj][st + w * 4];
        const float* bb = &vb[i0 + st + w * 4];
        s += v4.x + v4.y + v4.z + v4.w;
        sbias += v4.x * bb[0] + v4.y * bb[1] + v4.z * bb[2] + v4.w * bb[3];
        *(float4*)&dst[w * 4] = v4;
    }
    s += __shfl_xor_sync(0xffffffffu, s, 1);
    s += __shfl_xor_sync(0xffffffffu, s, 2);
    sbias += __shfl_xor_sync(0xffffffffu, sbias, 1);
    sbias += __shfl_xor_sync(0xffffffffu, sbias, 2);
    if ((tid & 3) == 0) {
        const int idx = ((b << 9) + j0 + jj) * 8 + blockIdx.y;
        g_ps[idx]  = s;
        g_psb[idx] = sbias;
    }
}

// ============================================================================
// reduce: S, TB -> g_inv = 1/S, g_ab = TB/S
// ============================================================================
__global__ __launch_bounds__(256) void reduce_kernel()
{
    const int idx = blockIdx.x * 256 + threadIdx.x;
    float S = 0.0f, TB = 0.0f;
#pragma unroll
    for (int r = 0; r < 8; r++) { S += g_ps[idx * 8 + r]; TB += g_psb[idx * 8 + r]; }
    g_inv[idx] = 1.0f / S;
    g_ab[idx]  = TB / S;
}

// ============================================================================
// Transposes
// ============================================================================
__global__ __launch_bounds__(256) void wt_kernel(const float* __restrict__ W)
{
    __shared__ float t[32][33];
    const int x0 = blockIdx.x * 32, y0 = blockIdx.y * 32;
    const int tx = threadIdx.x, ty = threadIdx.y;
#pragma unroll
    for (int r = 0; r < 32; r += 8) t[ty + r][tx] = W[(y0 + ty + r) * CCH + x0 + tx];
    __syncthreads();
#pragma unroll
    for (int r = 0; r < 32; r += 8)
        g_wt[(x0 + ty + r) * CCH + y0 + tx] = to_tf32(t[tx][ty + r]);
}

__global__ __launch_bounds__(256) void xt_kernel(const float* __restrict__ x)
{
    __shared__ float t[32][33];
    const int b = blockIdx.z;
    const float* in = x + (size_t)b * CCH * NPIX;
    float* out = g_xt + (size_t)b * NPIX * CCH;
    const int n0 = blockIdx.x * 32, c0 = blockIdx.y * 32;
    const int tx = threadIdx.x, ty = threadIdx.y;
#pragma unroll
    for (int r = 0; r < 32; r += 8) t[ty + r][tx] = in[(size_t)(c0 + ty + r) * NPIX + n0 + tx];
    __syncthreads();
#pragma unroll
    for (int r = 0; r < 32; r += 8)
        out[(size_t)(n0 + ty + r) * CCH + c0 + tx] = to_tf32(t[tx][ty + r]);
}

// ============================================================================
// gemm_mma: R5 tile shape (128x128, 8 warps 2x4, warp tile 64x32, BK=32),
// upgraded to 3-stage cp.async ring with ONE __syncthreads per stage.
// smem: 3 stages x (A 4096 + B 4096) floats = 96KB; 2 CTAs/SM.
// which==0: M = (At @ Wt) * (1/S_j), tf32 -> g_m
// which==1: out = M @ xT + ab
// ============================================================================
__global__ __launch_bounds__(256, 2) void gemm_mma(int which, float* __restrict__ outp)
{
    extern __shared__ __align__(16) float sm[];
    // stage buf: A at buf*8192, B at buf*8192 + 4096 (floats)

    const int b = blockIdx.z;
    const int col0 = blockIdx.x * 128, row0 = blockIdx.y * 128;

    const float* A; const float* B; float* C; int ldc;
    if (which == 0) {
        A = g_at + (size_t)b * CCH * CCH;
        B = g_wt;
        C = g_m + (size_t)b * CCH * CCH;
        ldc = CCH;
    } else {
        A = g_m + (size_t)b * CCH * CCH;
        B = g_xt + (size_t)b * NPIX * CCH;
        C = outp + (size_t)b * CCH * NPIX;
        ldc = NPIX;
    }
    const float* Ab = A + (size_t)row0 * CCH;
    const float* Bb = B + (size_t)col0 * CCH;

    const int tid = threadIdx.x;
    const int wid = tid >> 5, lid = tid & 31;
    const int gid = lid >> 2, tig = lid & 3;
    const int wm = wid >> 2, wn = wid & 3;

    const uint32_t sb = smem_u32(sm);
    const int ldrow = tid >> 3, ldch = tid & 7;
    const uint32_t sw = (uint32_t)((ldrow * 32 + (((ldch) ^ (ldrow & 7)) << 2)) * 4);

    auto issue = [&](int s, int buf) {
        const int k0 = s * 32;
        const uint32_t abase = sb + buf * 32768 + sw;
        const uint32_t bbase = sb + buf * 32768 + 16384 + sw;
#pragma unroll
        for (int q = 0; q < 4; q++) {
            int row = ldrow + q * 32;
            cpa16(abase + q * 32 * 128, &Ab[(size_t)row * CCH + k0 + ldch * 4]);
            cpa16(bbase + q * 32 * 128, &Bb[(size_t)row * CCH + k0 + ldch * 4]);
        }
        cpa_commit();
    };

    float acc[4][4][4] = {};
    int mrow[4], ncol[4];
#pragma unroll
    for (int i = 0; i < 4; i++) {
        mrow[i] = wm * 64 + i * 16 + gid;
        ncol[i] = wn * 32 + i * 8 + gid;
    }

    issue(0, 0);
    issue(1, 1);

    for (int s = 0; s < 16; s++) {
        const int buf = s % 3;
        if (s < 15) { asm volatile("cp.async.wait_group 1;" ::: "memory"); }
        else        { asm volatile("cp.async.wait_group 0;" ::: "memory"); }
        __syncthreads();
        if (s + 2 < 16) issue(s + 2, (s + 2) % 3);

        const float* as = sm + buf * 8192;
        const float* bs = as + 4096;
#pragma unroll
        for (int kk = 0; kk < 4; kk++) {
            const int c0ch = 2 * kk, c1ch = 2 * kk + 1;
            uint32_t af[4][4], bf[4][2];
#pragma unroll
            for (int mi = 0; mi < 4; mi++) {
                const int r1 = mrow[mi], r2 = r1 + 8;
                af[mi][0] = __float_as_uint(as[r1 * 32 + ((c0ch ^ (r1 & 7)) << 2) + tig]);
                af[mi][1] = __float_as_uint(as[r2 * 32 + ((c0ch ^ (r2 & 7)) << 2) + tig]);
                af[mi][2] = __float_as_uint(as[r1 * 32 + ((c1ch ^ (r1 & 7)) << 2) + tig]);
                af[mi][3] = __float_as_uint(as[r2 * 32 + ((c1ch ^ (r2 & 7)) << 2) + tig]);
            }
#pragma unroll
            for (int ni = 0; ni < 4; ni++) {
                const int cc = ncol[ni];
                bf[ni][0] = __float_as_uint(bs[cc * 32 + ((c0ch ^ (cc & 7)) << 2) + tig]);
                bf[ni][1] = __float_as_uint(bs[cc * 32 + ((c1ch ^ (cc & 7)) << 2) + tig]);
            }
#pragma unroll
            for (int mi = 0; mi < 4; mi++)
#pragma unroll
                for (int ni = 0; ni < 4; ni++)
                    mma_tf32(acc[mi][ni], af[mi], bf[ni]);
        }
    }

    // epilogue
#pragma unroll
    for (int mi = 0; mi < 4; mi++) {
        const int r1 = row0 + wm * 64 + mi * 16 + gid;
        const int r2 = r1 + 8;
        float s1, s2;
        if (which == 0) { s1 = g_inv[(b << 9) + r1]; s2 = g_inv[(b << 9) + r2]; }
        else            { s1 = g_ab [(b << 9) + r1]; s2 = g_ab [(b << 9) + r2]; }
#pragma unroll
        for (int ni = 0; ni < 4; ni++) {
            const int cc = col0 + wn * 32 + ni * 8 + tig * 2;
            float* p1 = &C[(size_t)r1 * ldc + cc];
            float* p2 = &C[(size_t)r2 * ldc + cc];
            float c0 = acc[mi][ni][0], c1 = acc[mi][ni][1];
            float c2 = acc[mi][ni][2], c3 = acc[mi][ni][3];
            if (which == 0) {
                c0 = to_tf32(c0 * s1); c1 = to_tf32(c1 * s1);
                c2 = to_tf32(c2 * s2); c3 = to_tf32(c3 * s2);
            } else {
                c0 += s1; c1 += s1; c2 += s2; c3 += s2;
            }
            *(float2*)p1 = make_float2(c0, c1);
            *(float2*)p2 = make_float2(c2, c3);
        }
    }
}

// ============================================================================
extern "C" void kernel_launch(void* const* d_in, const int* in_sizes, int n_in,
                              void* d_out, int out_size)
{
    const float* x  = (const float*)d_in[0];
    const float* qm = (const float*)d_in[1];
    const float* km = (const float*)d_in[2];
    const float* vw = (const float*)d_in[3];
    const float* vb = (const float*)d_in[4];
    float* out = (float*)d_out;

    cudaFuncSetAttribute(gemm_mma,    cudaFuncAttributeMaxDynamicSharedMemorySize, 98304);
    cudaFuncSetAttribute(qk3x_kernel, cudaFuncAttributeMaxDynamicSharedMemorySize, 131072);

    prep_b       <<<dim3(NPIX / 256, 128),           256>>>(qm, km);
    qk3x_kernel  <<<dim3(4, BATCH),                  256, 131072>>>(x);
    energy_kernel<<<dim3(CCH / 64, CCH / 64, BATCH), 256>>>(vb);
    reduce_kernel<<<dim3(BATCH * CCH / 256),         256>>>();
    wt_kernel    <<<dim3(16, 16),        dim3(32, 8)>>>(vw);
    xt_kernel    <<<dim3(32, 16, BATCH), dim3(32, 8)>>>(x);
    gemm_mma<<<dim3(CCH / 128,  CCH / 128, BATCH), 256, 98304>>>(0, nullptr);
    gemm_mma<<<dim3(NPIX / 128, CCH / 128, BATCH), 256, 98304>>>(1, out);
}

// round 10
// speedup vs baseline: 1.1149x; 1.0296x over previous
#include <cuda_runtime.h>
#include <cstdint>
#include <math.h>

#define BATCH 64
#define CCH   512
#define NPIX  1024
#define DD    64

// ---------------- scratch (static device arrays) ----------------
__device__ __align__(128) float g_q [BATCH * CCH * DD];
__device__ __align__(128) float g_k [BATCH * CCH * DD];
__device__ __align__(128) float g_at[(size_t)BATCH * CCH * CCH]; // unnormalized T, tf32
__device__ __align__(128) float g_m [(size_t)BATCH * CCH * CCH]; // M, tf32
__device__ __align__(128) float g_ab[BATCH * CCH];               // (T.b)/S per (b,j)
__device__ __align__(128) float g_inv[BATCH * CCH];              // 1/S per (b,j)
__device__ __align__(128) float g_ps [BATCH * CCH * 8];          // partial col sums
__device__ __align__(128) float g_psb[BATCH * CCH * 8];          // partial col bias dots
__device__ __align__(128) float g_wt[CCH * CCH];                 // W^T, tf32
__device__ __align__(128) float g_xt[(size_t)BATCH * NPIX * CCH];// x^T, tf32
__device__ __align__(128) float g_bhi[128 * NPIX];               // [Qm^T;Km^T] hi
__device__ __align__(128) float g_blo[128 * NPIX];               // [Qm^T;Km^T] lo

// ---------------- helpers ----------------
__device__ __forceinline__ float to_tf32(float x) {
    uint32_t u;
    asm("cvt.rna.tf32.f32 %0, %1;" : "=r"(u) : "f"(x));
    return __uint_as_float(u);
}
__device__ __forceinline__ uint32_t smem_u32(const void* p) {
    uint32_t a;
    asm("{ .reg .u64 t; cvta.to.shared.u64 t, %1; cvt.u32.u64 %0, t; }" : "=r"(a) : "l"(p));
    return a;
}
__device__ __forceinline__ void cpa16(uint32_t d, const void* g) {
    asm volatile("cp.async.cg.shared.global [%0], [%1], 16;" :: "r"(d), "l"(g) : "memory");
}
__device__ __forceinline__ void cpa_commit() {
    asm volatile("cp.async.commit_group;" ::: "memory");
}
__device__ __forceinline__ void mma_tf32(float* c, const uint32_t* a, const uint32_t* b) {
    asm volatile(
        "mma.sync.aligned.m16n8k8.row.col.f32.tf32.tf32.f32 "
        "{%0,%1,%2,%3}, {%4,%5,%6,%7}, {%8,%9}, {%0,%1,%2,%3};"
        : "+f"(c[0]), "+f"(c[1]), "+f"(c[2]), "+f"(c[3])
        : "r"(a[0]), "r"(a[1]), "r"(a[2]), "r"(a[3]), "r"(b[0]), "r"(b[1]));
}

// ============================================================================
// prep_b: g_bhi/g_blo[d'][n]: d'<64 -> Qm[n][d'], else Km[n][d'-64], split
// ============================================================================
__global__ __launch_bounds__(256) void prep_b(
    const float* __restrict__ qm, const float* __restrict__ km)
{
    const int n = blockIdx.x * 256 + threadIdx.x;
    const int d = blockIdx.y;
    float v = (d < 64) ? qm[n * 64 + d] : km[n * 64 + (d - 64)];
    float hi = to_tf32(v);
    g_bhi[d * NPIX + n] = hi;
    g_blo[d * NPIX + n] = v - hi;
}

// ============================================================================
// qk3x: [q|k] = x @ [Qm|Km] via 3xTF32 MMA. Tile 128(c) x 128(d'), BK=32.
// R5-proven version: double buffer, 128KB smem. grid (4, BATCH).
// ============================================================================
__global__ __launch_bounds__(256) void qk3x_kernel(const float* __restrict__ x)
{
    extern __shared__ __align__(16) float qs[];
    const int b = blockIdx.y;
    const int row0 = blockIdx.x * 128;
    const float* A = x + (size_t)b * CCH * NPIX + (size_t)row0 * NPIX;

    const int tid = threadIdx.x;
    const int wid = tid >> 5, lid = tid & 31;
    const int gid = lid >> 2, tig = lid & 3;
    const int wm = wid >> 2, wn = wid & 3;

    const uint32_t sb = smem_u32(qs);
    const int lr = tid >> 3, lc = tid & 7;

    float4 va[4];
    auto ldgA = [&](int s) {
        const int k0 = s * 32;
#pragma unroll
        for (int q = 0; q < 4; q++)
            va[q] = *(const float4*)&A[(size_t)(lr + q * 32) * NPIX + k0 + lc * 4];
    };
    auto stsA = [&](int buf) {
#pragma unroll
        for (int q = 0; q < 4; q++) {
            const int row = lr + q * 32;
            float* hi = qs + buf * 16384 + row * 32 + ((lc ^ (row & 7)) << 2);
            float* lo = hi + 4096;
            float4 h, l;
            h.x = to_tf32(va[q].x); l.x = va[q].x - h.x;
            h.y = to_tf32(va[q].y); l.y = va[q].y - h.y;
            h.z = to_tf32(va[q].z); l.z = va[q].z - h.z;
            h.w = to_tf32(va[q].w); l.w = va[q].w - h.w;
            *(float4*)hi = h;
            *(float4*)lo = l;
        }
    };
    auto cpaB = [&](int s, int buf) {
        const int k0 = s * 32;
#pragma unroll
        for (int q = 0; q < 4; q++) {
            const int row = lr + q * 32;
            const uint32_t off = (uint32_t)((row * 32 + ((lc ^ (row & 7)) << 2)) * 4);
            cpa16(sb + (buf * 16384 + 8192)  * 4 + off, &g_bhi[row * NPIX + k0 + lc * 4]);
            cpa16(sb + (buf * 16384 + 12288) * 4 + off, &g_blo[row * NPIX + k0 + lc * 4]);
        }
        cpa_commit();
    };

    float acc[4][4][4] = {};
    int mrow[4], ncol[4];
#pragma unroll
    for (int i = 0; i < 4; i++) {
        mrow[i] = wm * 64 + i * 16 + gid;
        ncol[i] = wn * 32 + i * 8 + gid;
    }

    ldgA(0);
    cpaB(0, 0);
    stsA(0);

    for (int s = 0; s < 32; s++) {
        const int buf = s & 1;
        asm volatile("cp.async.wait_group 0;" ::: "memory");
        __syncthreads();
        if (s < 31) { ldgA(s + 1); cpaB(s + 1, buf ^ 1); }

        const float* ahs = qs + buf * 16384;
        const float* als = ahs + 4096;
        const float* bhs = ahs + 8192;
        const float* bls = ahs + 12288;
#pragma unroll
        for (int kk = 0; kk < 4; kk++) {
            const int c0 = 2 * kk, c1 = 2 * kk + 1;
            uint32_t ah[4][4], al[4][4], bh[4][2], bl[4][2];
#pragma unroll
            for (int mi = 0; mi < 4; mi++) {
                const int r1 = mrow[mi], r2 = r1 + 8;
                const int o10 = r1 * 32 + ((c0 ^ (r1 & 7)) << 2) + tig;
                const int o20 = r2 * 32 + ((c0 ^ (r2 & 7)) << 2) + tig;
                const int o11 = r1 * 32 + ((c1 ^ (r1 & 7)) << 2) + tig;
                const int o21 = r2 * 32 + ((c1 ^ (r2 & 7)) << 2) + tig;
                ah[mi][0] = __float_as_uint(ahs[o10]); al[mi][0] = __float_as_uint(als[o10]);
                ah[mi][1] = __float_as_uint(ahs[o20]); al[mi][1] = __float_as_uint(als[o20]);
                ah[mi][2] = __float_as_uint(ahs[o11]); al[mi][2] = __float_as_uint(als[o11]);
                ah[mi][3] = __float_as_uint(ahs[o21]); al[mi][3] = __float_as_uint(als[o21]);
            }
#pragma unroll
            for (int ni = 0; ni < 4; ni++) {
                const int cc = ncol[ni];
                const int p0 = cc * 32 + ((c0 ^ (cc & 7)) << 2) + tig;
                const int p1 = cc * 32 + ((c1 ^ (cc & 7)) << 2) + tig;
                bh[ni][0] = __float_as_uint(bhs[p0]); bl[ni][0] = __float_as_uint(bls[p0]);
                bh[ni][1] = __float_as_uint(bhs[p1]); bl[ni][1] = __float_as_uint(bls[p1]);
            }
#pragma unroll
            for (int mi = 0; mi < 4; mi++)
#pragma unroll
                for (int ni = 0; ni < 4; ni++) {
                    mma_tf32(acc[mi][ni], ah[mi], bh[ni]);
                    mma_tf32(acc[mi][ni], ah[mi], bl[ni]);
                    mma_tf32(acc[mi][ni], al[mi], bh[ni]);
                }
        }
        __syncthreads();
        if (s < 31) stsA(buf ^ 1);
    }

#pragma unroll
    for (int mi = 0; mi < 4; mi++) {
        const int r1 = row0 + wm * 64 + mi * 16 + gid;
        const int r2 = r1 + 8;
#pragma unroll
        for (int ni = 0; ni < 4; ni++) {
            const int d = wn * 32 + ni * 8 + tig * 2;
            float* base = (d < 64) ? g_q : g_k;
            const int dc = d & 63;
            float* p1 = base + ((size_t)b * CCH + r1) * DD + dc;
            float* p2 = base + ((size_t)b * CCH + r2) * DD + dc;
            *(float2*)p1 = make_float2(acc[mi][ni][0], acc[mi][ni][1]);
            *(float2*)p2 = make_float2(acc[mi][ni][2], acc[mi][ni][3]);
        }
    }
}

// ============================================================================
// energy_mma: At[b][j][i] = tf32(T(e)), e = q.k^T via SINGLE-pass tf32 MMA.
// T = e>0 ? E : 1 (saturated); exact fp32 recompute when |e_approx| < 16
// (P ~ 1.6e-3). Tile 128(i) x 128(j), K=64 fully in smem. grid (4,4,64).
// smem: q_hi [128x64] at 0, k_hi at 8192 (floats); staging Cs[128][132]
// aliases operands after MMA (union = 16896 floats = 67584 B). 2 CTAs/SM.
// ============================================================================
#define E_CONST 2.71828182845904523536f

__global__ __launch_bounds__(256, 2) void energy_mma(const float* __restrict__ vb)
{
    extern __shared__ __align__(16) float es[];
    const int b  = blockIdx.z;
    const int j0 = blockIdx.x * 128;
    const int i0 = blockIdx.y * 128;
    const float* Q = g_q + ((size_t)b * CCH + i0) * DD;   // [128][64]
    const float* K = g_k + ((size_t)b * CCH + j0) * DD;   // [128][64]

    const int tid = threadIdx.x;
    const int wid = tid >> 5, lid = tid & 31;
    const int gid = lid >> 2, tig = lid & 3;
    const int wm = wid >> 2, wn = wid & 3;

    // load q,k hi-parts into swizzled smem: 128 rows x 16 chunks each
#pragma unroll
    for (int t = 0; t < 8; t++) {
        const int idx = tid + t * 256;
        const int row = idx >> 4, ch = idx & 15;
        float4 v = *(const float4*)&Q[(size_t)row * DD + ch * 4];
        float4 h;
        h.x = to_tf32(v.x); h.y = to_tf32(v.y); h.z = to_tf32(v.z); h.w = to_tf32(v.w);
        *(float4*)&es[row * 64 + ((ch ^ (row & 7)) << 2)] = h;
        float4 w = *(const float4*)&K[(size_t)row * DD + ch * 4];
        float4 g;
        g.x = to_tf32(w.x); g.y = to_tf32(w.y); g.z = to_tf32(w.z); g.w = to_tf32(w.w);
        *(float4*)&es[8192 + row * 64 + ((ch ^ (row & 7)) << 2)] = g;
    }
    __syncthreads();

    float acc[4][4][4] = {};
    int mrow[4], ncol[4];
#pragma unroll
    for (int i = 0; i < 4; i++) {
        mrow[i] = wm * 64 + i * 16 + gid;
        ncol[i] = wn * 32 + i * 8 + gid;
    }

    const float* qsm = es;
    const float* ksm = es + 8192;
#pragma unroll
    for (int kk = 0; kk < 8; kk++) {
        const int c0 = 2 * kk, c1 = 2 * kk + 1;
        uint32_t af[4][4], bf[4][2];
#pragma unroll
        for (int mi = 0; mi < 4; mi++) {
            const int r1 = mrow[mi], r2 = r1 + 8;
            af[mi][0] = __float_as_uint(qsm[r1 * 64 + ((c0 ^ (r1 & 7)) << 2) + tig]);
            af[mi][1] = __float_as_uint(qsm[r2 * 64 + ((c0 ^ (r2 & 7)) << 2) + tig]);
            af[mi][2] = __float_as_uint(qsm[r1 * 64 + ((c1 ^ (r1 & 7)) << 2) + tig]);
            af[mi][3] = __float_as_uint(qsm[r2 * 64 + ((c1 ^ (r2 & 7)) << 2) + tig]);
        }
#pragma unroll
        for (int ni = 0; ni < 4; ni++) {
            const int cc = ncol[ni];
            bf[ni][0] = __float_as_uint(ksm[cc * 64 + ((c0 ^ (cc & 7)) << 2) + tig]);
            bf[ni][1] = __float_as_uint(ksm[cc * 64 + ((c1 ^ (cc & 7)) << 2) + tig]);
        }
#pragma unroll
        for (int mi = 0; mi < 4; mi++)
#pragma unroll
            for (int ni = 0; ni < 4; ni++)
                mma_tf32(acc[mi][ni], af[mi], bf[ni]);
    }

    // transform in-place: T = e>0 ? E : 1; exact recompute for |e|<16
    auto xf = [&](float e, int gi, int gj) -> float {
        if (fabsf(e) < 16.0f) {
            const float* qr = g_q + ((size_t)b * CCH + gi) * DD;
            const float* kr = g_k + ((size_t)b * CCH + gj) * DD;
            float s = 0.0f;
#pragma unroll
            for (int d = 0; d < DD; d += 4) {
                float4 a4 = *(const float4*)&qr[d];
                float4 b4 = *(const float4*)&kr[d];
                s += a4.x * b4.x + a4.y * b4.y + a4.z * b4.z + a4.w * b4.w;
            }
            float sg = 1.0f / (1.0f + __expf(-s));
            return __expf(sg);
        }
        return (e > 0.0f) ? E_CONST : 1.0f;
    };
#pragma unroll
    for (int mi = 0; mi < 4; mi++) {
        const int r1 = mrow[mi], r2 = r1 + 8;
#pragma unroll
        for (int ni = 0; ni < 4; ni++) {
            const int cc = wn * 32 + ni * 8 + tig * 2;
            acc[mi][ni][0] = to_tf32(xf(acc[mi][ni][0], i0 + r1, j0 + cc));
            acc[mi][ni][1] = to_tf32(xf(acc[mi][ni][1], i0 + r1, j0 + cc + 1));
            acc[mi][ni][2] = to_tf32(xf(acc[mi][ni][2], i0 + r2, j0 + cc));
            acc[mi][ni][3] = to_tf32(xf(acc[mi][ni][3], i0 + r2, j0 + cc + 1));
        }
    }

    // stage transposed Cs[j][i] (overwrites operand smem)
    __syncthreads();
#pragma unroll
    for (int mi = 0; mi < 4; mi++) {
        const int r1 = mrow[mi], r2 = r1 + 8;
#pragma unroll
        for (int ni = 0; ni < 4; ni++) {
            const int cc = wn * 32 + ni * 8 + tig * 2;
            es[(cc + 0) * 132 + r1] = acc[mi][ni][0];
            es[(cc + 1) * 132 + r1] = acc[mi][ni][1];
            es[(cc + 0) * 132 + r2] = acc[mi][ni][2];
            es[(cc + 1) * 132 + r2] = acc[mi][ni][3];
        }
    }
    __syncthreads();

    // coalesced output + partial column sums (4 i-tiles per (b,j))
    const int jj = tid >> 1;           // 0..127
    const int half = (tid & 1) * 64;   // i offset within tile
    float* dst = g_at + ((size_t)b * CCH + j0 + jj) * CCH + i0 + half;
    float s = 0.0f, sb2 = 0.0f;
#pragma unroll
    for (int w = 0; w < 16; w++) {
        float4 v4 = *(float4*)&es[jj * 132 + half + w * 4];
        const float* bb = &vb[i0 + half + w * 4];
        s   += v4.x + v4.y + v4.z + v4.w;
        sb2 += v4.x * bb[0] + v4.y * bb[1] + v4.z * bb[2] + v4.w * bb[3];
        *(float4*)&dst[w * 4] = v4;
    }
    s   += __shfl_xor_sync(0xffffffffu, s,   1);
    sb2 += __shfl_xor_sync(0xffffffffu, sb2, 1);
    if ((tid & 1) == 0) {
        const int idx = ((b << 9) + j0 + jj) * 4 + blockIdx.y;
        g_ps[idx]  = s;
        g_psb[idx] = sb2;
    }
}

// ============================================================================
// reduce: S, TB -> g_inv = 1/S, g_ab = TB/S   (4 partials per row now)
// ============================================================================
__global__ __launch_bounds__(256) void reduce_kernel()
{
    const int idx = blockIdx.x * 256 + threadIdx.x;
    float S = 0.0f, TB = 0.0f;
#pragma unroll
    for (int r = 0; r < 4; r++) { S += g_ps[idx * 4 + r]; TB += g_psb[idx * 4 + r]; }
    g_inv[idx] = 1.0f / S;
    g_ab[idx]  = TB / S;
}

// ============================================================================
// Transposes
// ============================================================================
__global__ __launch_bounds__(256) void wt_kernel(const float* __restrict__ W)
{
    __shared__ float t[32][33];
    const int x0 = blockIdx.x * 32, y0 = blockIdx.y * 32;
    const int tx = threadIdx.x, ty = threadIdx.y;
#pragma unroll
    for (int r = 0; r < 32; r += 8) t[ty + r][tx] = W[(y0 + ty + r) * CCH + x0 + tx];
    __syncthreads();
#pragma unroll
    for (int r = 0; r < 32; r += 8)
        g_wt[(x0 + ty + r) * CCH + y0 + tx] = to_tf32(t[tx][ty + r]);
}

__global__ __launch_bounds__(256) void xt_kernel(const float* __restrict__ x)
{
    __shared__ float t[32][33];
    const int b = blockIdx.z;
    const float* in = x + (size_t)b * CCH * NPIX;
    float* out = g_xt + (size_t)b * NPIX * CCH;
    const int n0 = blockIdx.x * 32, c0 = blockIdx.y * 32;
    const int tx = threadIdx.x, ty = threadIdx.y;
#pragma unroll
    for (int r = 0; r < 32; r += 8) t[ty + r][tx] = in[(size_t)(c0 + ty + r) * NPIX + n0 + tx];
    __syncthreads();
#pragma unroll
    for (int r = 0; r < 32; r += 8)
        out[(size_t)(n0 + ty + r) * CCH + c0 + tx] = to_tf32(t[tx][ty + r]);
}

// ============================================================================
// gemm_mma: exact R5-proven version. 128x128, BK=32, double buffer, 2 CTA/SM.
// which==0: M = (At @ Wt) * (1/S_j), tf32 -> g_m
// which==1: out = M @ xT + ab
// ============================================================================
__global__ __launch_bounds__(256, 2) void gemm_mma(int which, float* __restrict__ outp)
{
    extern __shared__ __align__(16) float sm[];

    const int b = blockIdx.z;
    const int col0 = blockIdx.x * 128, row0 = blockIdx.y * 128;

    const float* A; const float* B; float* C; int ldc;
    if (which == 0) {
        A = g_at + (size_t)b * CCH * CCH;
        B = g_wt;
        C = g_m + (size_t)b * CCH * CCH;
        ldc = CCH;
    } else {
        A = g_m + (size_t)b * CCH * CCH;
        B = g_xt + (size_t)b * NPIX * CCH;
        C = outp + (size_t)b * CCH * NPIX;
        ldc = NPIX;
    }
    const float* Ab = A + (size_t)row0 * CCH;
    const float* Bb = B + (size_t)col0 * CCH;

    const int tid = threadIdx.x;
    const int wid = tid >> 5, lid = tid & 31;
    const int gid = lid >> 2, tig = lid & 3;
    const int wm = wid >> 2, wn = wid & 3;

    const uint32_t sb = smem_u32(sm);
    const int ldrow = tid >> 3, ldch = tid & 7;
    const uint32_t sw = (uint32_t)((ldrow * 32 + (((ldch) ^ (ldrow & 7)) << 2)) * 4);

    auto issue = [&](int s, int buf) {
        const int k0 = s * 32;
        const uint32_t abase = sb + buf * 16384 + sw;
        const uint32_t bbase = sb + 32768 + buf * 16384 + sw;
#pragma unroll
        for (int q = 0; q < 4; q++) {
            int row = ldrow + q * 32;
            cpa16(abase + q * 32 * 128, &Ab[(size_t)row * CCH + k0 + ldch * 4]);
            cpa16(bbase + q * 32 * 128, &Bb[(size_t)row * CCH + k0 + ldch * 4]);
        }
        cpa_commit();
    };

    float acc[4][4][4] = {};
    int mrow[4], ncol[4];
#pragma unroll
    for (int i = 0; i < 4; i++) {
        mrow[i] = wm * 64 + i * 16 + gid;
        ncol[i] = wn * 32 + i * 8 + gid;
    }

    issue(0, 0);

    for (int s = 0; s < 16; s++) {
        const int buf = s & 1;
        if (s < 15) issue(s + 1, buf ^ 1);
        if (s < 15) { asm volatile("cp.async.wait_group 1;" ::: "memory"); }
        else        { asm volatile("cp.async.wait_group 0;" ::: "memory"); }
        __syncthreads();

        const float* as = sm + buf * 4096;
        const float* bs = sm + 8192 + buf * 4096;
#pragma unroll
        for (int kk = 0; kk < 4; kk++) {
            const int c0ch = 2 * kk, c1ch = 2 * kk + 1;
            uint32_t af[4][4], bf[4][2];
#pragma unroll
            for (int mi = 0; mi < 4; mi++) {
                const int r1 = mrow[mi], r2 = r1 + 8;
                af[mi][0] = __float_as_uint(as[r1 * 32 + ((c0ch ^ (r1 & 7)) << 2) + tig]);
                af[mi][1] = __float_as_uint(as[r2 * 32 + ((c0ch ^ (r2 & 7)) << 2) + tig]);
                af[mi][2] = __float_as_uint(as[r1 * 32 + ((c1ch ^ (r1 & 7)) << 2) + tig]);
                af[mi][3] = __float_as_uint(as[r2 * 32 + ((c1ch ^ (r2 & 7)) << 2) + tig]);
            }
#pragma unroll
            for (int ni = 0; ni < 4; ni++) {
                const int cc = ncol[ni];
                bf[ni][0] = __float_as_uint(bs[cc * 32 + ((c0ch ^ (cc & 7)) << 2) + tig]);
                bf[ni][1] = __float_as_uint(bs[cc * 32 + ((c1ch ^ (cc & 7)) << 2) + tig]);
            }
#pragma unroll
            for (int mi = 0; mi < 4; mi++)
#pragma unroll
                for (int ni = 0; ni < 4; ni++)
                    mma_tf32(acc[mi][ni], af[mi], bf[ni]);
        }
        __syncthreads();
    }

#pragma unroll
    for (int mi = 0; mi < 4; mi++) {
        const int r1 = row0 + wm * 64 + mi * 16 + gid;
        const int r2 = r1 + 8;
        float s1, s2;
        if (which == 0) { s1 = g_inv[(b << 9) + r1]; s2 = g_inv[(b << 9) + r2]; }
        else            { s1 = g_ab [(b << 9) + r1]; s2 = g_ab [(b << 9) + r2]; }
#pragma unroll
        for (int ni = 0; ni < 4; ni++) {
            const int cc = col0 + wn * 32 + ni * 8 + tig * 2;
            float* p1 = &C[(size_t)r1 * ldc + cc];
            float* p2 = &C[(size_t)r2 * ldc + cc];
            float c0 = acc[mi][ni][0], c1 = acc[mi][ni][1];
            float c2 = acc[mi][ni][2], c3 = acc[mi][ni][3];
            if (which == 0) {
                c0 = to_tf32(c0 * s1); c1 = to_tf32(c1 * s1);
                c2 = to_tf32(c2 * s2); c3 = to_tf32(c3 * s2);
            } else {
                c0 += s1; c1 += s1; c2 += s2; c3 += s2;
            }
            *(float2*)p1 = make_float2(c0, c1);
            *(float2*)p2 = make_float2(c2, c3);
        }
    }
}

// ============================================================================
extern "C" void kernel_launch(void* const* d_in, const int* in_sizes, int n_in,
                              void* d_out, int out_size)
{
    const float* x  = (const float*)d_in[0];
    const float* qm = (const float*)d_in[1];
    const float* km = (const float*)d_in[2];
    const float* vw = (const float*)d_in[3];
    const float* vb = (const float*)d_in[4];
    float* out = (float*)d_out;

    cudaFuncSetAttribute(gemm_mma,    cudaFuncAttributeMaxDynamicSharedMemorySize, 65536);
    cudaFuncSetAttribute(qk3x_kernel, cudaFuncAttributeMaxDynamicSharedMemorySize, 131072);
    cudaFuncSetAttribute(energy_mma,  cudaFuncAttributeMaxDynamicSharedMemorySize, 67584);

    prep_b       <<<dim3(NPIX / 256, 128),       256>>>(qm, km);
    qk3x_kernel  <<<dim3(4, BATCH),              256, 131072>>>(x);
    energy_mma   <<<dim3(4, 4, BATCH),           256, 67584>>>(vb);
    reduce_kernel<<<dim3(BATCH * CCH / 256),     256>>>();
    wt_kernel    <<<dim3(16, 16),        dim3(32, 8)>>>(vw);
    xt_kernel    <<<dim3(32, 16, BATCH), dim3(32, 8)>>>(x);
    gemm_mma<<<dim3(CCH / 128,  CCH / 128, BATCH), 256, 65536>>>(0, nullptr);
    gemm_mma<<<dim3(NPIX / 128, CCH / 128, BATCH), 256, 65536>>>(1, out);
}

// round 11
// speedup vs baseline: 1.1185x; 1.0033x over previous
#include <cuda_runtime.h>
#include <cstdint>
#include <math.h>

#define BATCH 64
#define CCH   512
#define NPIX  1024
#define DD    64

// ---------------- scratch (static device arrays) ----------------
__device__ __align__(128) float g_q [BATCH * CCH * DD];
__device__ __align__(128) float g_k [BATCH * CCH * DD];
__device__ __align__(128) float g_at[(size_t)BATCH * CCH * CCH]; // unnormalized T, tf32
__device__ __align__(128) float g_m [(size_t)BATCH * CCH * CCH]; // M, tf32
__device__ __align__(128) float g_ab[BATCH * CCH];               // (T.b)/S per (b,j)
__device__ __align__(128) float g_inv[BATCH * CCH];              // 1/S per (b,j)
__device__ __align__(128) float g_ps [BATCH * CCH * 8];          // partial col sums
__device__ __align__(128) float g_psb[BATCH * CCH * 8];          // partial col bias dots
__device__ __align__(128) float g_wt[CCH * CCH];                 // W^T, tf32
__device__ __align__(128) float g_xt[(size_t)BATCH * NPIX * CCH];// x^T, tf32
__device__ __align__(128) float g_bhi[128 * NPIX];               // [Qm^T;Km^T] hi
__device__ __align__(128) float g_blo[128 * NPIX];               // [Qm^T;Km^T] lo

// ---------------- helpers ----------------
__device__ __forceinline__ float to_tf32(float x) {
    uint32_t u;
    asm("cvt.rna.tf32.f32 %0, %1;" : "=r"(u) : "f"(x));
    return __uint_as_float(u);
}
__device__ __forceinline__ uint32_t smem_u32(const void* p) {
    uint32_t a;
    asm("{ .reg .u64 t; cvta.to.shared.u64 t, %1; cvt.u32.u64 %0, t; }" : "=r"(a) : "l"(p));
    return a;
}
__device__ __forceinline__ void cpa16(uint32_t d, const void* g) {
    asm volatile("cp.async.cg.shared.global [%0], [%1], 16;" :: "r"(d), "l"(g) : "memory");
}
__device__ __forceinline__ void cpa_commit() {
    asm volatile("cp.async.commit_group;" ::: "memory");
}
__device__ __forceinline__ void mma_tf32(float* c, const uint32_t* a, const uint32_t* b) {
    asm volatile(
        "mma.sync.aligned.m16n8k8.row.col.f32.tf32.tf32.f32 "
        "{%0,%1,%2,%3}, {%4,%5,%6,%7}, {%8,%9}, {%0,%1,%2,%3};"
        : "+f"(c[0]), "+f"(c[1]), "+f"(c[2]), "+f"(c[3])
        : "r"(a[0]), "r"(a[1]), "r"(a[2]), "r"(a[3]), "r"(b[0]), "r"(b[1]));
}

// ============================================================================
// prep_b: g_bhi/g_blo[d'][n]: d'<64 -> Qm[n][d'], else Km[n][d'-64], split
// ============================================================================
__global__ __launch_bounds__(256) void prep_b(
    const float* __restrict__ qm, const float* __restrict__ km)
{
    const int n = blockIdx.x * 256 + threadIdx.x;
    const int d = blockIdx.y;
    float v = (d < 64) ? qm[n * 64 + d] : km[n * 64 + (d - 64)];
    float hi = to_tf32(v);
    g_bhi[d * NPIX + n] = hi;
    g_blo[d * NPIX + n] = v - hi;
}

// ============================================================================
// qk3x: [q|k] = x @ [Qm|Km] via 3xTF32 MMA. Tile 128(c) x 128(d'), BK=32.
// R5-proven version: double buffer, 128KB smem. grid (4, BATCH).
// ============================================================================
__global__ __launch_bounds__(256) void qk3x_kernel(const float* __restrict__ x)
{
    extern __shared__ __align__(16) float qs[];
    const int b = blockIdx.y;
    const int row0 = blockIdx.x * 128;
    const float* A = x + (size_t)b * CCH * NPIX + (size_t)row0 * NPIX;

    const int tid = threadIdx.x;
    const int wid = tid >> 5, lid = tid & 31;
    const int gid = lid >> 2, tig = lid & 3;
    const int wm = wid >> 2, wn = wid & 3;

    const uint32_t sb = smem_u32(qs);
    const int lr = tid >> 3, lc = tid & 7;

    float4 va[4];
    auto ldgA = [&](int s) {
        const int k0 = s * 32;
#pragma unroll
        for (int q = 0; q < 4; q++)
            va[q] = *(const float4*)&A[(size_t)(lr + q * 32) * NPIX + k0 + lc * 4];
    };
    auto stsA = [&](int buf) {
#pragma unroll
        for (int q = 0; q < 4; q++) {
            const int row = lr + q * 32;
            float* hi = qs + buf * 16384 + row * 32 + ((lc ^ (row & 7)) << 2);
            float* lo = hi + 4096;
            float4 h, l;
            h.x = to_tf32(va[q].x); l.x = va[q].x - h.x;
            h.y = to_tf32(va[q].y); l.y = va[q].y - h.y;
            h.z = to_tf32(va[q].z); l.z = va[q].z - h.z;
            h.w = to_tf32(va[q].w); l.w = va[q].w - h.w;
            *(float4*)hi = h;
            *(float4*)lo = l;
        }
    };
    auto cpaB = [&](int s, int buf) {
        const int k0 = s * 32;
#pragma unroll
        for (int q = 0; q < 4; q++) {
            const int row = lr + q * 32;
            const uint32_t off = (uint32_t)((row * 32 + ((lc ^ (row & 7)) << 2)) * 4);
            cpa16(sb + (buf * 16384 + 8192)  * 4 + off, &g_bhi[row * NPIX + k0 + lc * 4]);
            cpa16(sb + (buf * 16384 + 12288) * 4 + off, &g_blo[row * NPIX + k0 + lc * 4]);
        }
        cpa_commit();
    };

    float acc[4][4][4] = {};
    int mrow[4], ncol[4];
#pragma unroll
    for (int i = 0; i < 4; i++) {
        mrow[i] = wm * 64 + i * 16 + gid;
        ncol[i] = wn * 32 + i * 8 + gid;
    }

    ldgA(0);
    cpaB(0, 0);
    stsA(0);

    for (int s = 0; s < 32; s++) {
        const int buf = s & 1;
        asm volatile("cp.async.wait_group 0;" ::: "memory");
        __syncthreads();
        if (s < 31) { ldgA(s + 1); cpaB(s + 1, buf ^ 1); }

        const float* ahs = qs + buf * 16384;
        const float* als = ahs + 4096;
        const float* bhs = ahs + 8192;
        const float* bls = ahs + 12288;
#pragma unroll
        for (int kk = 0; kk < 4; kk++) {
            const int c0 = 2 * kk, c1 = 2 * kk + 1;
            uint32_t ah[4][4], al[4][4], bh[4][2], bl[4][2];
#pragma unroll
            for (int mi = 0; mi < 4; mi++) {
                const int r1 = mrow[mi], r2 = r1 + 8;
                const int o10 = r1 * 32 + ((c0 ^ (r1 & 7)) << 2) + tig;
                const int o20 = r2 * 32 + ((c0 ^ (r2 & 7)) << 2) + tig;
                const int o11 = r1 * 32 + ((c1 ^ (r1 & 7)) << 2) + tig;
                const int o21 = r2 * 32 + ((c1 ^ (r2 & 7)) << 2) + tig;
                ah[mi][0] = __float_as_uint(ahs[o10]); al[mi][0] = __float_as_uint(als[o10]);
                ah[mi][1] = __float_as_uint(ahs[o20]); al[mi][1] = __float_as_uint(als[o20]);
                ah[mi][2] = __float_as_uint(ahs[o11]); al[mi][2] = __float_as_uint(als[o11]);
                ah[mi][3] = __float_as_uint(ahs[o21]); al[mi][3] = __float_as_uint(als[o21]);
            }
#pragma unroll
            for (int ni = 0; ni < 4; ni++) {
                const int cc = ncol[ni];
                const int p0 = cc * 32 + ((c0 ^ (cc & 7)) << 2) + tig;
                const int p1 = cc * 32 + ((c1 ^ (cc & 7)) << 2) + tig;
                bh[ni][0] = __float_as_uint(bhs[p0]); bl[ni][0] = __float_as_uint(bls[p0]);
                bh[ni][1] = __float_as_uint(bhs[p1]); bl[ni][1] = __float_as_uint(bls[p1]);
            }
#pragma unroll
            for (int mi = 0; mi < 4; mi++)
#pragma unroll
                for (int ni = 0; ni < 4; ni++) {
                    mma_tf32(acc[mi][ni], ah[mi], bh[ni]);
                    mma_tf32(acc[mi][ni], ah[mi], bl[ni]);
                    mma_tf32(acc[mi][ni], al[mi], bh[ni]);
                }
        }
        __syncthreads();
        if (s < 31) stsA(buf ^ 1);
    }

#pragma unroll
    for (int mi = 0; mi < 4; mi++) {
        const int r1 = row0 + wm * 64 + mi * 16 + gid;
        const int r2 = r1 + 8;
#pragma unroll
        for (int ni = 0; ni < 4; ni++) {
            const int d = wn * 32 + ni * 8 + tig * 2;
            float* base = (d < 64) ? g_q : g_k;
            const int dc = d & 63;
            float* p1 = base + ((size_t)b * CCH + r1) * DD + dc;
            float* p2 = base + ((size_t)b * CCH + r2) * DD + dc;
            *(float2*)p1 = make_float2(acc[mi][ni][0], acc[mi][ni][1]);
            *(float2*)p2 = make_float2(acc[mi][ni][2], acc[mi][ni][3]);
        }
    }
}

// ============================================================================
// energy_mma: At[b][j][i] = tf32(T(e)), e = q.k^T via SINGLE-pass tf32 MMA.
// T = e>0 ? E : 1 (saturated); exact fp32 recompute when |e_approx| < 16.
// Tile 128(i) x 128(j), K=64 in smem. grid (4,4,64). 2 CTAs/SM.
// ============================================================================
#define E_CONST 2.71828182845904523536f

__global__ __launch_bounds__(256, 2) void energy_mma(const float* __restrict__ vb)
{
    extern __shared__ __align__(16) float es[];
    const int b  = blockIdx.z;
    const int j0 = blockIdx.x * 128;
    const int i0 = blockIdx.y * 128;
    const float* Q = g_q + ((size_t)b * CCH + i0) * DD;
    const float* K = g_k + ((size_t)b * CCH + j0) * DD;

    const int tid = threadIdx.x;
    const int wid = tid >> 5, lid = tid & 31;
    const int gid = lid >> 2, tig = lid & 3;
    const int wm = wid >> 2, wn = wid & 3;

#pragma unroll
    for (int t = 0; t < 8; t++) {
        const int idx = tid + t * 256;
        const int row = idx >> 4, ch = idx & 15;
        float4 v = *(const float4*)&Q[(size_t)row * DD + ch * 4];
        float4 h;
        h.x = to_tf32(v.x); h.y = to_tf32(v.y); h.z = to_tf32(v.z); h.w = to_tf32(v.w);
        *(float4*)&es[row * 64 + ((ch ^ (row & 7)) << 2)] = h;
        float4 w = *(const float4*)&K[(size_t)row * DD + ch * 4];
        float4 g;
        g.x = to_tf32(w.x); g.y = to_tf32(w.y); g.z = to_tf32(w.z); g.w = to_tf32(w.w);
        *(float4*)&es[8192 + row * 64 + ((ch ^ (row & 7)) << 2)] = g;
    }
    __syncthreads();

    float acc[4][4][4] = {};
    int mrow[4], ncol[4];
#pragma unroll
    for (int i = 0; i < 4; i++) {
        mrow[i] = wm * 64 + i * 16 + gid;
        ncol[i] = wn * 32 + i * 8 + gid;
    }

    const float* qsm = es;
    const float* ksm = es + 8192;
#pragma unroll
    for (int kk = 0; kk < 8; kk++) {
        const int c0 = 2 * kk, c1 = 2 * kk + 1;
        uint32_t af[4][4], bf[4][2];
#pragma unroll
        for (int mi = 0; mi < 4; mi++) {
            const int r1 = mrow[mi], r2 = r1 + 8;
            af[mi][0] = __float_as_uint(qsm[r1 * 64 + ((c0 ^ (r1 & 7)) << 2) + tig]);
            af[mi][1] = __float_as_uint(qsm[r2 * 64 + ((c0 ^ (r2 & 7)) << 2) + tig]);
            af[mi][2] = __float_as_uint(qsm[r1 * 64 + ((c1 ^ (r1 & 7)) << 2) + tig]);
            af[mi][3] = __float_as_uint(qsm[r2 * 64 + ((c1 ^ (r2 & 7)) << 2) + tig]);
        }
#pragma unroll
        for (int ni = 0; ni < 4; ni++) {
            const int cc = ncol[ni];
            bf[ni][0] = __float_as_uint(ksm[cc * 64 + ((c0 ^ (cc & 7)) << 2) + tig]);
            bf[ni][1] = __float_as_uint(ksm[cc * 64 + ((c1 ^ (cc & 7)) << 2) + tig]);
        }
#pragma unroll
        for (int mi = 0; mi < 4; mi++)
#pragma unroll
            for (int ni = 0; ni < 4; ni++)
                mma_tf32(acc[mi][ni], af[mi], bf[ni]);
    }

    auto xf = [&](float e, int gi, int gj) -> float {
        if (fabsf(e) < 16.0f) {
            const float* qr = g_q + ((size_t)b * CCH + gi) * DD;
            const float* kr = g_k + ((size_t)b * CCH + gj) * DD;
            float s = 0.0f;
#pragma unroll
            for (int d = 0; d < DD; d += 4) {
                float4 a4 = *(const float4*)&qr[d];
                float4 b4 = *(const float4*)&kr[d];
                s += a4.x * b4.x + a4.y * b4.y + a4.z * b4.z + a4.w * b4.w;
            }
            float sg = 1.0f / (1.0f + __expf(-s));
            return __expf(sg);
        }
        return (e > 0.0f) ? E_CONST : 1.0f;
    };
#pragma unroll
    for (int mi = 0; mi < 4; mi++) {
        const int r1 = mrow[mi], r2 = r1 + 8;
#pragma unroll
        for (int ni = 0; ni < 4; ni++) {
            const int cc = wn * 32 + ni * 8 + tig * 2;
            acc[mi][ni][0] = to_tf32(xf(acc[mi][ni][0], i0 + r1, j0 + cc));
            acc[mi][ni][1] = to_tf32(xf(acc[mi][ni][1], i0 + r1, j0 + cc + 1));
            acc[mi][ni][2] = to_tf32(xf(acc[mi][ni][2], i0 + r2, j0 + cc));
            acc[mi][ni][3] = to_tf32(xf(acc[mi][ni][3], i0 + r2, j0 + cc + 1));
        }
    }

    __syncthreads();
#pragma unroll
    for (int mi = 0; mi < 4; mi++) {
        const int r1 = mrow[mi], r2 = r1 + 8;
#pragma unroll
        for (int ni = 0; ni < 4; ni++) {
            const int cc = wn * 32 + ni * 8 + tig * 2;
            es[(cc + 0) * 132 + r1] = acc[mi][ni][0];
            es[(cc + 1) * 132 + r1] = acc[mi][ni][1];
            es[(cc + 0) * 132 + r2] = acc[mi][ni][2];
            es[(cc + 1) * 132 + r2] = acc[mi][ni][3];
        }
    }
    __syncthreads();

    const int jj = tid >> 1;
    const int half = (tid & 1) * 64;
    float* dst = g_at + ((size_t)b * CCH + j0 + jj) * CCH + i0 + half;
    float s = 0.0f, sb2 = 0.0f;
#pragma unroll
    for (int w = 0; w < 16; w++) {
        float4 v4 = *(float4*)&es[jj * 132 + half + w * 4];
        const float* bb = &vb[i0 + half + w * 4];
        s   += v4.x + v4.y + v4.z + v4.w;
        sb2 += v4.x * bb[0] + v4.y * bb[1] + v4.z * bb[2] + v4.w * bb[3];
        *(float4*)&dst[w * 4] = v4;
    }
    s   += __shfl_xor_sync(0xffffffffu, s,   1);
    sb2 += __shfl_xor_sync(0xffffffffu, sb2, 1);
    if ((tid & 1) == 0) {
        const int idx = ((b << 9) + j0 + jj) * 4 + blockIdx.y;
        g_ps[idx]  = s;
        g_psb[idx] = sb2;
    }
}

// ============================================================================
// reduce: S, TB -> g_inv = 1/S, g_ab = TB/S   (4 partials per row)
// ============================================================================
__global__ __launch_bounds__(256) void reduce_kernel()
{
    const int idx = blockIdx.x * 256 + threadIdx.x;
    float S = 0.0f, TB = 0.0f;
#pragma unroll
    for (int r = 0; r < 4; r++) { S += g_ps[idx * 4 + r]; TB += g_psb[idx * 4 + r]; }
    g_inv[idx] = 1.0f / S;
    g_ab[idx]  = TB / S;
}

// ============================================================================
// Transposes
// ============================================================================
__global__ __launch_bounds__(256) void wt_kernel(const float* __restrict__ W)
{
    __shared__ float t[32][33];
    const int x0 = blockIdx.x * 32, y0 = blockIdx.y * 32;
    const int tx = threadIdx.x, ty = threadIdx.y;
#pragma unroll
    for (int r = 0; r < 32; r += 8) t[ty + r][tx] = W[(y0 + ty + r) * CCH + x0 + tx];
    __syncthreads();
#pragma unroll
    for (int r = 0; r < 32; r += 8)
        g_wt[(x0 + ty + r) * CCH + y0 + tx] = to_tf32(t[tx][ty + r]);
}

__global__ __launch_bounds__(256) void xt_kernel(const float* __restrict__ x)
{
    __shared__ float t[32][33];
    const int b = blockIdx.z;
    const float* in = x + (size_t)b * CCH * NPIX;
    float* out = g_xt + (size_t)b * NPIX * CCH;
    const int n0 = blockIdx.x * 32, c0 = blockIdx.y * 32;
    const int tx = threadIdx.x, ty = threadIdx.y;
#pragma unroll
    for (int r = 0; r < 32; r += 8) t[ty + r][tx] = in[(size_t)(c0 + ty + r) * NPIX + n0 + tx];
    __syncthreads();
#pragma unroll
    for (int r = 0; r < 32; r += 8)
        out[(size_t)(n0 + ty + r) * CCH + c0 + tx] = to_tf32(t[tx][ty + r]);
}

// ============================================================================
// gemm_mma: R5-proven. 128x128, BK=32, double buffer, 2 CTA/SM.
// which==0: M = (At @ Wt) * (1/S_j), tf32 -> g_m
// which==1: out = M @ xT + ab
// ============================================================================
__global__ __launch_bounds__(256, 2) void gemm_mma(int which, float* __restrict__ outp)
{
    extern __shared__ __align__(16) float sm[];

    const int b = blockIdx.z;
    const int col0 = blockIdx.x * 128, row0 = blockIdx.y * 128;

    const float* A; const float* B; float* C; int ldc;
    if (which == 0) {
        A = g_at + (size_t)b * CCH * CCH;
        B = g_wt;
        C = g_m + (size_t)b * CCH * CCH;
        ldc = CCH;
    } else {
        A = g_m + (size_t)b * CCH * CCH;
        B = g_xt + (size_t)b * NPIX * CCH;
        C = outp + (size_t)b * CCH * NPIX;
        ldc = NPIX;
    }
    const float* Ab = A + (size_t)row0 * CCH;
    const float* Bb = B + (size_t)col0 * CCH;

    const int tid = threadIdx.x;
    const int wid = tid >> 5, lid = tid & 31;
    const int gid = lid >> 2, tig = lid & 3;
    const int wm = wid >> 2, wn = wid & 3;

    const uint32_t sb = smem_u32(sm);
    const int ldrow = tid >> 3, ldch = tid & 7;
    const uint32_t sw = (uint32_t)((ldrow * 32 + (((ldch) ^ (ldrow & 7)) << 2)) * 4);

    auto issue = [&](int s, int buf) {
        const int k0 = s * 32;
        const uint32_t abase = sb + buf * 16384 + sw;
        const uint32_t bbase = sb + 32768 + buf * 16384 + sw;
#pragma unroll
        for (int q = 0; q < 4; q++) {
            int row = ldrow + q * 32;
            cpa16(abase + q * 32 * 128, &Ab[(size_t)row * CCH + k0 + ldch * 4]);
            cpa16(bbase + q * 32 * 128, &Bb[(size_t)row * CCH + k0 + ldch * 4]);
        }
        cpa_commit();
    };

    float acc[4][4][4] = {};
    int mrow[4], ncol[4];
#pragma unroll
    for (int i = 0; i < 4; i++) {
        mrow[i] = wm * 64 + i * 16 + gid;
        ncol[i] = wn * 32 + i * 8 + gid;
    }

    issue(0, 0);

    for (int s = 0; s < 16; s++) {
        const int buf = s & 1;
        if (s < 15) issue(s + 1, buf ^ 1);
        if (s < 15) { asm volatile("cp.async.wait_group 1;" ::: "memory"); }
        else        { asm volatile("cp.async.wait_group 0;" ::: "memory"); }
        __syncthreads();

        const float* as = sm + buf * 4096;
        const float* bs = sm + 8192 + buf * 4096;
#pragma unroll
        for (int kk = 0; kk < 4; kk++) {
            const int c0ch = 2 * kk, c1ch = 2 * kk + 1;
            uint32_t af[4][4], bf[4][2];
#pragma unroll
            for (int mi = 0; mi < 4; mi++) {
                const int r1 = mrow[mi], r2 = r1 + 8;
                af[mi][0] = __float_as_uint(as[r1 * 32 + ((c0ch ^ (r1 & 7)) << 2) + tig]);
                af[mi][1] = __float_as_uint(as[r2 * 32 + ((c0ch ^ (r2 & 7)) << 2) + tig]);
                af[mi][2] = __float_as_uint(as[r1 * 32 + ((c1ch ^ (r1 & 7)) << 2) + tig]);
                af[mi][3] = __float_as_uint(as[r2 * 32 + ((c1ch ^ (r2 & 7)) << 2) + tig]);
            }
#pragma unroll
            for (int ni = 0; ni < 4; ni++) {
                const int cc = ncol[ni];
                bf[ni][0] = __float_as_uint(bs[cc * 32 + ((c0ch ^ (cc & 7)) << 2) + tig]);
                bf[ni][1] = __float_as_uint(bs[cc * 32 + ((c1ch ^ (cc & 7)) << 2) + tig]);
            }
#pragma unroll
            for (int mi = 0; mi < 4; mi++)
#pragma unroll
                for (int ni = 0; ni < 4; ni++)
                    mma_tf32(acc[mi][ni], af[mi], bf[ni]);
        }
        __syncthreads();
    }

#pragma unroll
    for (int mi = 0; mi < 4; mi++) {
        const int r1 = row0 + wm * 64 + mi * 16 + gid;
        const int r2 = r1 + 8;
        float s1, s2;
        if (which == 0) { s1 = g_inv[(b << 9) + r1]; s2 = g_inv[(b << 9) + r2]; }
        else            { s1 = g_ab [(b << 9) + r1]; s2 = g_ab [(b << 9) + r2]; }
#pragma unroll
        for (int ni = 0; ni < 4; ni++) {
            const int cc = col0 + wn * 32 + ni * 8 + tig * 2;
            float* p1 = &C[(size_t)r1 * ldc + cc];
            float* p2 = &C[(size_t)r2 * ldc + cc];
            float c0 = acc[mi][ni][0], c1 = acc[mi][ni][1];
            float c2 = acc[mi][ni][2], c3 = acc[mi][ni][3];
            if (which == 0) {
                c0 = to_tf32(c0 * s1); c1 = to_tf32(c1 * s1);
                c2 = to_tf32(c2 * s2); c3 = to_tf32(c3 * s2);
            } else {
                c0 += s1; c1 += s1; c2 += s2; c3 += s2;
            }
            *(float2*)p1 = make_float2(c0, c1);
            *(float2*)p2 = make_float2(c2, c3);
        }
    }
}

// ============================================================================
// kernel_launch: forked-stream capture. Side branch runs wt + xt (feed only
// K3/K4) concurrently with prep_b -> qk3x -> energy -> reduce. Streams/events
// are host objects created fresh each call (graph replay never re-runs this),
// never destroyed mid-capture. Events use DisableTiming (graph requirement).
// ============================================================================
extern "C" void kernel_launch(void* const* d_in, const int* in_sizes, int n_in,
                              void* d_out, int out_size)
{
    const float* x  = (const float*)d_in[0];
    const float* qm = (const float*)d_in[1];
    const float* km = (const float*)d_in[2];
    const float* vw = (const float*)d_in[3];
    const float* vb = (const float*)d_in[4];
    float* out = (float*)d_out;

    cudaFuncSetAttribute(gemm_mma,    cudaFuncAttributeMaxDynamicSharedMemorySize, 65536);
    cudaFuncSetAttribute(qk3x_kernel, cudaFuncAttributeMaxDynamicSharedMemorySize, 131072);
    cudaFuncSetAttribute(energy_mma,  cudaFuncAttributeMaxDynamicSharedMemorySize, 67584);

    cudaStream_t s1;
    cudaEvent_t eFork, eJoin;
    cudaStreamCreateWithFlags(&s1, cudaStreamNonBlocking);
    cudaEventCreateWithFlags(&eFork, cudaEventDisableTiming);
    cudaEventCreateWithFlags(&eJoin, cudaEventDisableTiming);

    // fork: side branch (wt, xt) independent of the attention chain
    cudaEventRecord(eFork, 0);
    cudaStreamWaitEvent(s1, eFork, 0);
    wt_kernel<<<dim3(16, 16),        dim3(32, 8), 0, s1>>>(vw);
    xt_kernel<<<dim3(32, 16, BATCH), dim3(32, 8), 0, s1>>>(x);
    cudaEventRecord(eJoin, s1);

    // main chain on default stream
    prep_b       <<<dim3(NPIX / 256, 128),       256>>>(qm, km);
    qk3x_kernel  <<<dim3(4, BATCH),              256, 131072>>>(x);
    energy_mma   <<<dim3(4, 4, BATCH),           256, 67584>>>(vb);
    reduce_kernel<<<dim3(BATCH * CCH / 256),     256>>>();

    // join: K3 needs wt; K4 needs xt
    cudaStreamWaitEvent(0, eJoin, 0);
    gemm_mma<<<dim3(CCH / 128,  CCH / 128, BATCH), 256, 65536>>>(0, nullptr);
    gemm_mma<<<dim3(NPIX / 128, CCH / 128, BATCH), 256, 65536>>>(1, out);
}